// round 10
// baseline (speedup 1.0000x reference)
#include <cuda_runtime.h>
#include <cuda_bf16.h>
#include <cstdint>
#include <math.h>

// ---------------- problem constants ----------------
#define BB  2
#define TT  2048
#define DD  2048
#define NHH 16
#define HDD 128
#define MM  (BB*TT)
#define ELEMS ((long)BB*TT*DD)
#define ESZ ((long)BB*NHH*TT*TT)

// GEMM tiling
#define GBM 128
#define GBN 128
#define GBK 32
#define GTHREADS 256

// SMEM: per stage 4 halves (AH, AL, BH, BL), 128 rows x 80B pitch each
#define PITCH 80
#define HALF_SZ 10240
#define STG 40960
#define NSTAGE 4
#define GEMM_SMEM (NSTAGE*STG)   // 163840 bytes

// epilogue modes (bitmask)
#define EPI_C      1   // write fp32 C (+resid)
#define EPI_SPLIT  2   // write split bf16 OH/OL of val
#define EPI_SWIGLU 4   // val = resid*sigmoid(resid)*val, then split write

// ---------------- scratch (static device memory) ----------------
__device__ __nv_bfloat16 g_nH[ELEMS], g_nL[ELEMS];
__device__ __nv_bfloat16 g_qkvH[3*ELEMS], g_qkvL[3*ELEMS];
__device__ __nv_bfloat16 g_vTH[ELEMS], g_vTL[ELEMS];
__device__ __nv_bfloat16 g_ctxH[ELEMS], g_ctxL[ELEMS];
__device__ float g_h2[ELEMS];
__device__ float g_x1[ELEMS];
__device__ __nv_bfloat16 g_x1H[ELEMS], g_x1L[ELEMS];
__device__ __nv_bfloat16 g_gH[ELEMS], g_gL[ELEMS];
__device__ __nv_bfloat16 g_wH[7L*DD*DD], g_wL[7L*DD*DD];
__device__ __nv_bfloat16 g_eH[ESZ], g_eL[ESZ];

// ---------------- helpers ----------------
__device__ __forceinline__ uint32_t smem_u32(const void* p) {
    uint32_t a;
    asm("{ .reg .u64 t; cvta.to.shared.u64 t, %1; cvt.u32.u64 %0, t; }" : "=r"(a) : "l"(p));
    return a;
}
__device__ __forceinline__ void ldsm4(uint32_t* r, uint32_t addr) {
    asm volatile("ldmatrix.sync.aligned.m8n8.x4.shared.b16 {%0,%1,%2,%3}, [%4];"
        : "=r"(r[0]), "=r"(r[1]), "=r"(r[2]), "=r"(r[3]) : "r"(addr));
}
__device__ __forceinline__ void mma_bf16(float* c, const uint32_t* a, const uint32_t* b) {
    asm volatile(
        "mma.sync.aligned.m16n8k16.row.col.f32.bf16.bf16.f32 "
        "{%0,%1,%2,%3}, {%4,%5,%6,%7}, {%8,%9}, {%0,%1,%2,%3};"
        : "+f"(c[0]), "+f"(c[1]), "+f"(c[2]), "+f"(c[3])
        : "r"(a[0]), "r"(a[1]), "r"(a[2]), "r"(a[3]), "r"(b[0]), "r"(b[1]));
}
__device__ __forceinline__ void cpasync16(uint32_t dst, const void* src) {
    asm volatile("cp.async.cg.shared.global [%0], [%1], 16;" :: "r"(dst), "l"(src));
}
#define CP_COMMIT() asm volatile("cp.async.commit_group;" ::: "memory")
#define CP_WAIT(N)  asm volatile("cp.async.wait_group %0;" :: "n"(N) : "memory")

__device__ __forceinline__ void split1(float v, __nv_bfloat16& h, __nv_bfloat16& l) {
    h = __float2bfloat16(v);
    l = __float2bfloat16(v - __bfloat162float(h));
}

// ---------------- bf16-split GEMM (4-stage cp.async pipeline) ----------------
__global__ __launch_bounds__(GTHREADS) void gemm_bf16s(
    const __nv_bfloat16* __restrict__ AH, const __nv_bfloat16* __restrict__ AL,
    const __nv_bfloat16* __restrict__ BH, const __nv_bfloat16* __restrict__ BL,
    const float* __restrict__ bias, const float* __restrict__ bias2, const float* __restrict__ bias3,
    const float* __restrict__ resid,
    float* __restrict__ C, __nv_bfloat16* __restrict__ OH, __nv_bfloat16* __restrict__ OL,
    int K, int lda, int ldb, int ldc,
    long sAb, long sAh, long sBb, long sBh, long sCb, long sCh, int nh,
    float alpha, int mode)
{
    extern __shared__ char smem[];
    const uint32_t sbase = smem_u32(smem);
    const int tid = threadIdx.x;
    const int wid = tid >> 5;
    const int lane = tid & 31;

    int z = blockIdx.z;
    int bz = z / nh, hz = z % nh;
    const long aoff = (long)bz * sAb + (long)hz * sAh;
    const long boff = (long)bz * sBb + (long)hz * sBh;
    const long coff = (long)bz * sCb + (long)hz * sCh;
    AH += aoff; AL += aoff;
    BH += boff; BL += boff;

    const float* bb = bias;
    if (bias2) bb = (hz == 0) ? bias : ((hz == 1) ? bias2 : bias3);

    const int bm = blockIdx.y * GBM;
    const int bn = blockIdx.x * GBN;

    const int wm = wid >> 2;
    const int wn = wid & 3;

    const uint32_t aOff = (uint32_t)(wm * 64 + (lane & 15)) * PITCH + (lane >> 4) * 16;
    const uint32_t bOff = 2 * HALF_SZ
        + (uint32_t)(wn * 32 + ((lane >> 4) << 3) + (lane & 7)) * PITCH + ((lane >> 3) & 1) * 16;

    const int cid0 = tid * 2, cid1 = cid0 + 1;
    const int r0 = cid0 >> 2, c0 = cid0 & 3;
    const int r1 = cid1 >> 2, c1 = cid1 & 3;
    const __nv_bfloat16* aH0 = AH + (long)(bm + r0) * lda + c0 * 8;
    const __nv_bfloat16* aH1 = AH + (long)(bm + r1) * lda + c1 * 8;
    const __nv_bfloat16* aL0 = AL + (long)(bm + r0) * lda + c0 * 8;
    const __nv_bfloat16* aL1 = AL + (long)(bm + r1) * lda + c1 * 8;
    const __nv_bfloat16* bH0 = BH + (long)(bn + r0) * ldb + c0 * 8;
    const __nv_bfloat16* bH1 = BH + (long)(bn + r1) * ldb + c1 * 8;
    const __nv_bfloat16* bL0 = BL + (long)(bn + r0) * ldb + c0 * 8;
    const __nv_bfloat16* bL1 = BL + (long)(bn + r1) * ldb + c1 * 8;
    const uint32_t d0 = (uint32_t)(r0 * PITCH + c0 * 16);
    const uint32_t d1 = (uint32_t)(r1 * PITCH + c1 * 16);

#define ISSUE_STAGE(SIDX, KO) do {                                   \
        uint32_t s_ = sbase + (uint32_t)(SIDX) * STG;                \
        long ko_ = (KO);                                             \
        cpasync16(s_ + d0,             aH0 + ko_);                   \
        cpasync16(s_ + d1,             aH1 + ko_);                   \
        cpasync16(s_ + HALF_SZ + d0,   aL0 + ko_);                   \
        cpasync16(s_ + HALF_SZ + d1,   aL1 + ko_);                   \
        cpasync16(s_ + 2*HALF_SZ + d0, bH0 + ko_);                   \
        cpasync16(s_ + 2*HALF_SZ + d1, bH1 + ko_);                   \
        cpasync16(s_ + 3*HALF_SZ + d0, bL0 + ko_);                   \
        cpasync16(s_ + 3*HALF_SZ + d1, bL1 + ko_);                   \
    } while (0)

    float acc[4][4][4];
    #pragma unroll
    for (int i = 0; i < 4; i++)
        #pragma unroll
        for (int j = 0; j < 4; j++)
            #pragma unroll
            for (int r = 0; r < 4; r++) acc[i][j][r] = 0.f;

    const int NKI = K / GBK;

    #pragma unroll
    for (int s = 0; s < NSTAGE - 1; s++) {
        if (s < NKI) ISSUE_STAGE(s, (long)s * GBK);
        CP_COMMIT();
    }

    for (int i = 0; i < NKI; i++) {
        CP_WAIT(2);
        __syncthreads();

        if (i + 3 < NKI) ISSUE_STAGE((i + 3) & (NSTAGE - 1), (long)(i + 3) * GBK);
        CP_COMMIT();

        const uint32_t sb = sbase + (uint32_t)(i & (NSTAGE - 1)) * STG;
        #pragma unroll
        for (int ks = 0; ks < 2; ks++) {
            uint32_t afh[4][4], afl[4][4];
            uint32_t bfh[2][4], bfl[2][4];
            #pragma unroll
            for (int mf = 0; mf < 4; mf++) {
                uint32_t ad = sb + aOff + mf * (16 * PITCH) + ks * 32;
                ldsm4(afh[mf], ad);
                ldsm4(afl[mf], ad + HALF_SZ);
            }
            #pragma unroll
            for (int np = 0; np < 2; np++) {
                uint32_t bd = sb + bOff + np * (16 * PITCH) + ks * 32;
                ldsm4(bfh[np], bd);
                ldsm4(bfl[np], bd + HALF_SZ);
            }
            #pragma unroll
            for (int mf = 0; mf < 4; mf++) {
                #pragma unroll
                for (int nf = 0; nf < 4; nf++) {
                    const int np = nf >> 1;
                    const int pr = (nf & 1) * 2;
                    mma_bf16(acc[mf][nf], afh[mf], &bfh[np][pr]);
                    mma_bf16(acc[mf][nf], afh[mf], &bfl[np][pr]);
                    mma_bf16(acc[mf][nf], afl[mf], &bfh[np][pr]);
                }
            }
        }
    }
#undef ISSUE_STAGE

    float* Cp = C ? C + coff : nullptr;
    __nv_bfloat16* OHp = OH ? OH + coff : nullptr;
    __nv_bfloat16* OLp = OL ? OL + coff : nullptr;
    const int g = lane >> 2;
    const int t = lane & 3;
    #pragma unroll
    for (int mf = 0; mf < 4; mf++) {
        #pragma unroll
        for (int nf = 0; nf < 4; nf++) {
            int row0 = bm + wm * 64 + mf * 16 + g;
            int col = bn + wn * 32 + nf * 8 + t * 2;
            float2 v0, v1;
            v0.x = acc[mf][nf][0] * alpha;
            v0.y = acc[mf][nf][1] * alpha;
            v1.x = acc[mf][nf][2] * alpha;
            v1.y = acc[mf][nf][3] * alpha;
            if (bb) {
                float2 bbv = *(const float2*)(bb + col);
                v0.x += bbv.x; v0.y += bbv.y;
                v1.x += bbv.x; v1.y += bbv.y;
            }
            long o0 = (long)row0 * ldc + col;
            long o1 = (long)(row0 + 8) * ldc + col;
            if (mode & EPI_SWIGLU) {
                float2 rr0 = *(const float2*)(resid + o0);
                float2 rr1 = *(const float2*)(resid + o1);
                v0.x = rr0.x * (1.0f / (1.0f + expf(-rr0.x))) * v0.x;
                v0.y = rr0.y * (1.0f / (1.0f + expf(-rr0.y))) * v0.y;
                v1.x = rr1.x * (1.0f / (1.0f + expf(-rr1.x))) * v1.x;
                v1.y = rr1.y * (1.0f / (1.0f + expf(-rr1.y))) * v1.y;
            }
            if (mode & EPI_SPLIT) {
                __nv_bfloat162 h0, l0, h1, l1;
                split1(v0.x, h0.x, l0.x); split1(v0.y, h0.y, l0.y);
                split1(v1.x, h1.x, l1.x); split1(v1.y, h1.y, l1.y);
                *(__nv_bfloat162*)(OHp + o0) = h0;
                *(__nv_bfloat162*)(OLp + o0) = l0;
                *(__nv_bfloat162*)(OHp + o1) = h1;
                *(__nv_bfloat162*)(OLp + o1) = l1;
            }
            if (mode & EPI_C) {
                if (resid) {
                    float2 rr0 = *(const float2*)(resid + o0);
                    float2 rr1 = *(const float2*)(resid + o1);
                    v0.x += rr0.x; v0.y += rr0.y;
                    v1.x += rr1.x; v1.y += rr1.y;
                }
                *(float2*)(Cp + o0) = v0;
                *(float2*)(Cp + o1) = v1;
            }
        }
    }
}

// ---------------- fused softmax + PV GEMM ----------------
__device__ __forceinline__ void bf2f8(uint4 uh, uint4 ul, float* e) {
    const __nv_bfloat162* h2 = (const __nv_bfloat162*)&uh;
    const __nv_bfloat162* l2 = (const __nv_bfloat162*)&ul;
    #pragma unroll
    for (int p = 0; p < 4; p++) {
        float2 a = __bfloat1622float2(h2[p]);
        float2 b = __bfloat1622float2(l2[p]);
        e[2*p]   = a.x + b.x;
        e[2*p+1] = a.y + b.y;
    }
}

__global__ __launch_bounds__(256) void attn_pv(
    const __nv_bfloat16* __restrict__ eH, const __nv_bfloat16* __restrict__ eL,
    const __nv_bfloat16* __restrict__ vTH, const __nv_bfloat16* __restrict__ vTL,
    __nv_bfloat16* __restrict__ ctxH, __nv_bfloat16* __restrict__ ctxL)
{
    __shared__ char smem[4*HALF_SZ + 1024];
    const uint32_t sbase = smem_u32(smem);
    const int tid = threadIdx.x;
    const int wid = tid >> 5;
    const int lane = tid & 31;
    const int z = blockIdx.z;             // b*NHH + h
    const int bzb = z / NHH, hzh = z % NHH;
    const int bm = blockIdx.y * 128;      // q block

    const __nv_bfloat16* eHb = eH + (long)z * TT * TT + (long)bm * TT;
    const __nv_bfloat16* eLb = eL + (long)z * TT * TT + (long)bm * TT;
    const __nv_bfloat16* vHb = vTH + (long)z * HDD * TT;
    const __nv_bfloat16* vLb = vTL + (long)z * HDD * TT;

    float* sm_m  = (float*)(smem + 4*HALF_SZ);
    float* sm_is = sm_m + 128;

    const int row = tid >> 1;
    const int hs = tid & 1;

    // ---- phase 1: per-row max & sum over 2048 keys (each thread: half a row) ----
    {
        const __nv_bfloat16* ph = eHb + (long)row * TT + hs * 1024;
        const __nv_bfloat16* pl = eLb + (long)row * TT + hs * 1024;
        float m = -1e30f, s = 0.f;
        for (int it = 0; it < 128; it++) {
            uint4 uh = *(const uint4*)(ph + it * 8);
            uint4 ul = *(const uint4*)(pl + it * 8);
            float e[8];
            bf2f8(uh, ul, e);
            float ml = e[0];
            #pragma unroll
            for (int j = 1; j < 8; j++) ml = fmaxf(ml, e[j]);
            float mn = fmaxf(m, ml);
            s *= expf(m - mn);
            #pragma unroll
            for (int j = 0; j < 8; j++) s += expf(e[j] - mn);
            m = mn;
        }
        float m2 = __shfl_xor_sync(0xffffffffu, m, 1);
        float s2 = __shfl_xor_sync(0xffffffffu, s, 1);
        float mm = fmaxf(m, m2);
        float ss = s * expf(m - mm) + s2 * expf(m2 - mm);
        if (hs == 0) { sm_m[row] = mm; sm_is[row] = 1.0f / ss; }
    }
    __syncthreads();
    const float mrow = sm_m[row];

    // ---- phase 2: mainloop. A = exp(e-m) staged in-register; B = vT via LDG+STS ----
    const __nv_bfloat16* aHp = eHb + (long)row * TT + hs * 16;
    const __nv_bfloat16* aLp = eLb + (long)row * TT + hs * 16;
    const __nv_bfloat16* bHp = vHb + (long)row * TT + hs * 16;
    const __nv_bfloat16* bLp = vLb + (long)row * TT + hs * 16;
    const int sAc = row * PITCH + hs * 32;
    const int sBc = 2 * HALF_SZ + row * PITCH + hs * 32;

    const int wm = wid >> 2;
    const int wn = wid & 3;
    const uint32_t aOff = sbase + (uint32_t)(wm * 64 + (lane & 15)) * PITCH + (lane >> 4) * 16;
    const uint32_t bOff = sbase + 2 * HALF_SZ
        + (uint32_t)(wn * 32 + ((lane >> 4) << 3) + (lane & 7)) * PITCH + ((lane >> 3) & 1) * 16;

    float acc[4][4][4];
    #pragma unroll
    for (int i = 0; i < 4; i++)
        #pragma unroll
        for (int j = 0; j < 4; j++)
            #pragma unroll
            for (int r = 0; r < 4; r++) acc[i][j][r] = 0.f;

    uint4 rah0, rah1, ral0, ral1, rbh0, rbh1, rbl0, rbl1;
    uint32_t phh[8], pll[8];

#define LOAD_RAW(I) do {                                  \
        long k_ = (long)(I) * GBK;                        \
        rah0 = *(const uint4*)(aHp + k_);                 \
        rah1 = *(const uint4*)(aHp + k_ + 8);             \
        ral0 = *(const uint4*)(aLp + k_);                 \
        ral1 = *(const uint4*)(aLp + k_ + 8);             \
        rbh0 = *(const uint4*)(bHp + k_);                 \
        rbh1 = *(const uint4*)(bHp + k_ + 8);             \
        rbl0 = *(const uint4*)(bLp + k_);                 \
        rbl1 = *(const uint4*)(bLp + k_ + 8);             \
    } while (0)

#define CONVERT() do {                                                     \
        float e_[8];                                                       \
        bf2f8(rah0, ral0, e_);                                             \
        _Pragma("unroll")                                                  \
        for (int p_ = 0; p_ < 4; p_++) {                                   \
            float p0 = expf(e_[2*p_]   - mrow);                            \
            float p1 = expf(e_[2*p_+1] - mrow);                            \
            __nv_bfloat16 h0, l0, h1, l1;                                  \
            split1(p0, h0, l0); split1(p1, h1, l1);                        \
            __nv_bfloat162 hp = __halves2bfloat162(h0, h1);                \
            __nv_bfloat162 lp = __halves2bfloat162(l0, l1);                \
            phh[p_] = *(uint32_t*)&hp; pll[p_] = *(uint32_t*)&lp;          \
        }                                                                  \
        bf2f8(rah1, ral1, e_);                                             \
        _Pragma("unroll")                                                  \
        for (int p_ = 0; p_ < 4; p_++) {                                   \
            float p0 = expf(e_[2*p_]   - mrow);                            \
            float p1 = expf(e_[2*p_+1] - mrow);                            \
            __nv_bfloat16 h0, l0, h1, l1;                                  \
            split1(p0, h0, l0); split1(p1, h1, l1);                        \
            __nv_bfloat162 hp = __halves2bfloat162(h0, h1);                \
            __nv_bfloat162 lp = __halves2bfloat162(l0, l1);                \
            phh[4+p_] = *(uint32_t*)&hp; pll[4+p_] = *(uint32_t*)&lp;      \
        }                                                                  \
    } while (0)

#define STORE_STAGE() do {                                                            \
        *(uint4*)(smem + sAc)            = make_uint4(phh[0], phh[1], phh[2], phh[3]);\
        *(uint4*)(smem + sAc + 16)       = make_uint4(phh[4], phh[5], phh[6], phh[7]);\
        *(uint4*)(smem + HALF_SZ + sAc)      = make_uint4(pll[0], pll[1], pll[2], pll[3]);\
        *(uint4*)(smem + HALF_SZ + sAc + 16) = make_uint4(pll[4], pll[5], pll[6], pll[7]);\
        *(uint4*)(smem + sBc)            = rbh0;                                      \
        *(uint4*)(smem + sBc + 16)       = rbh1;                                      \
        *(uint4*)(smem + HALF_SZ + sBc)      = rbl0;                                  \
        *(uint4*)(smem + HALF_SZ + sBc + 16) = rbl1;                                  \
    } while (0)

    const int NKI = TT / GBK;   // 64
    LOAD_RAW(0);
    CONVERT();
    STORE_STAGE();

    for (int i = 0; i < NKI; i++) {
        __syncthreads();    // stage i visible
        if (i + 1 < NKI) LOAD_RAW(i + 1);

        #pragma unroll
        for (int ks = 0; ks < 2; ks++) {
            uint32_t afh[4][4], afl[4][4];
            uint32_t bfh[2][4], bfl[2][4];
            #pragma unroll
            for (int mf = 0; mf < 4; mf++) {
                uint32_t ad = aOff + mf * (16 * PITCH) + ks * 32;
                ldsm4(afh[mf], ad);
                ldsm4(afl[mf], ad + HALF_SZ);
            }
            #pragma unroll
            for (int np = 0; np < 2; np++) {
                uint32_t bd = bOff + np * (16 * PITCH) + ks * 32;
                ldsm4(bfh[np], bd);
                ldsm4(bfl[np], bd + HALF_SZ);
            }
            #pragma unroll
            for (int mf = 0; mf < 4; mf++) {
                #pragma unroll
                for (int nf = 0; nf < 4; nf++) {
                    const int np = nf >> 1;
                    const int pr = (nf & 1) * 2;
                    mma_bf16(acc[mf][nf], afh[mf], &bfh[np][pr]);
                    mma_bf16(acc[mf][nf], afh[mf], &bfl[np][pr]);
                    mma_bf16(acc[mf][nf], afl[mf], &bfh[np][pr]);
                }
            }
        }

        if (i + 1 < NKI) CONVERT();
        __syncthreads();    // reads of stage i done
        if (i + 1 < NKI) STORE_STAGE();
    }
#undef LOAD_RAW
#undef CONVERT
#undef STORE_STAGE

    // epilogue: scale by 1/s, split-write ctx [b, t, h, d]
    const long coff = (long)bzb * TT * DD + (long)hzh * HDD;
    const int g = lane >> 2;
    const int t = lane & 3;
    #pragma unroll
    for (int mf = 0; mf < 4; mf++) {
        int rl0 = wm * 64 + mf * 16 + g;
        int rl1 = rl0 + 8;
        float is0 = sm_is[rl0];
        float is1 = sm_is[rl1];
        #pragma unroll
        for (int nf = 0; nf < 4; nf++) {
            int col = wn * 32 + nf * 8 + t * 2;
            float2 v0, v1;
            v0.x = acc[mf][nf][0] * is0;
            v0.y = acc[mf][nf][1] * is0;
            v1.x = acc[mf][nf][2] * is1;
            v1.y = acc[mf][nf][3] * is1;
            long o0 = coff + (long)(bm + rl0) * DD + col;
            long o1 = coff + (long)(bm + rl1) * DD + col;
            __nv_bfloat162 h0, l0, h1, l1;
            split1(v0.x, h0.x, l0.x); split1(v0.y, h0.y, l0.y);
            split1(v1.x, h1.x, l1.x); split1(v1.y, h1.y, l1.y);
            *(__nv_bfloat162*)(ctxH + o0) = h0;
            *(__nv_bfloat162*)(ctxL + o0) = l0;
            *(__nv_bfloat162*)(ctxH + o1) = h1;
            *(__nv_bfloat162*)(ctxL + o1) = l1;
        }
    }
}

// ---------------- transpose + split (fp32 input) ----------------
__global__ __launch_bounds__(256) void transpose_split(
    const float* __restrict__ in, __nv_bfloat16* __restrict__ oH, __nv_bfloat16* __restrict__ oL,
    int ldin, int ldout, long sInB, long sInH, long sOutB, long sOutH, int nh)
{
    __shared__ float tile[32][33];
    int z = blockIdx.z, bz = z / nh, hz = z % nh;
    in += (long)bz * sInB + (long)hz * sInH;
    long ob = (long)bz * sOutB + (long)hz * sOutH;
    oH += ob; oL += ob;
    int c0 = blockIdx.x << 5, r0 = blockIdx.y << 5;
    int tx = threadIdx.x & 31, ty = threadIdx.x >> 5;
    #pragma unroll
    for (int j = 0; j < 4; j++)
        tile[ty + j * 8][tx] = in[(long)(r0 + ty + j * 8) * ldin + c0 + tx];
    __syncthreads();
    #pragma unroll
    for (int j = 0; j < 4; j++) {
        float val = tile[tx][ty + j * 8];
        __nv_bfloat16 h, l;
        split1(val, h, l);
        long o = (long)(c0 + ty + j * 8) * ldout + r0 + tx;
        oH[o] = h; oL[o] = l;
    }
}

// ---------------- transpose + split (bf16 hi/lo input) ----------------
__global__ __launch_bounds__(256) void transpose_split_bf2(
    const __nv_bfloat16* __restrict__ inH, const __nv_bfloat16* __restrict__ inL,
    __nv_bfloat16* __restrict__ oH, __nv_bfloat16* __restrict__ oL,
    int ldin, int ldout, long sInB, long sInH, long sOutB, long sOutH, int nh)
{
    __shared__ float tile[32][33];
    int z = blockIdx.z, bz = z / nh, hz = z % nh;
    long ib = (long)bz * sInB + (long)hz * sInH;
    inH += ib; inL += ib;
    long ob = (long)bz * sOutB + (long)hz * sOutH;
    oH += ob; oL += ob;
    int c0 = blockIdx.x << 5, r0 = blockIdx.y << 5;
    int tx = threadIdx.x & 31, ty = threadIdx.x >> 5;
    #pragma unroll
    for (int j = 0; j < 4; j++) {
        long idx = (long)(r0 + ty + j * 8) * ldin + c0 + tx;
        tile[ty + j * 8][tx] = __bfloat162float(inH[idx]) + __bfloat162float(inL[idx]);
    }
    __syncthreads();
    #pragma unroll
    for (int j = 0; j < 4; j++) {
        float val = tile[tx][ty + j * 8];
        __nv_bfloat16 h, l;
        split1(val, h, l);
        long o = (long)(c0 + ty + j * 8) * ldout + r0 + tx;
        oH[o] = h; oL[o] = l;
    }
}

// ---------------- block reduction ----------------
__device__ __forceinline__ float block_reduce_sum(float v) {
    __shared__ float sh[8];
    #pragma unroll
    for (int o = 16; o > 0; o >>= 1) v += __shfl_xor_sync(0xffffffffu, v, o);
    int w = threadIdx.x >> 5;
    if ((threadIdx.x & 31) == 0) sh[w] = v;
    __syncthreads();
    if (threadIdx.x < 8) {
        v = sh[threadIdx.x];
        #pragma unroll
        for (int o = 4; o > 0; o >>= 1) v += __shfl_xor_sync(0xffu, v, o);
        if (threadIdx.x == 0) sh[0] = v;
    }
    __syncthreads();
    float r = sh[0];
    __syncthreads();
    return r;
}

// ---------------- RMSNorm -> split bf16 ----------------
__global__ __launch_bounds__(256) void rmsnorm_split(
    const float* __restrict__ x, const float* __restrict__ scale,
    __nv_bfloat16* __restrict__ yH, __nv_bfloat16* __restrict__ yL)
{
    long row = blockIdx.x;
    const float* xr = x + row * (long)DD;
    float vals[8];
    float ss = 0.f;
    #pragma unroll
    for (int i = 0; i < 8; i++) {
        int idx = threadIdx.x + i * 256;
        float v = xr[idx];
        vals[i] = v;
        ss += v * v;
    }
    ss = block_reduce_sum(ss);
    float r = rsqrtf(ss * (1.0f / DD) + 1e-5f);
    long base = row * (long)DD;
    #pragma unroll
    for (int i = 0; i < 8; i++) {
        int idx = threadIdx.x + i * 256;
        float v = scale[idx] * vals[i] * r;
        __nv_bfloat16 h, l;
        split1(v, h, l);
        yH[base + idx] = h; yL[base + idx] = l;
    }
}

// ---------------- launcher ----------------
extern "C" void kernel_launch(void* const* d_in, const int* in_sizes, int n_in,
                              void* d_out, int out_size) {
    const float* x      = (const float*)d_in[0];
    const float* Wq     = (const float*)d_in[1];
    const float* bq     = (const float*)d_in[2];
    const float* Wk     = (const float*)d_in[3];
    const float* bk     = (const float*)d_in[4];
    const float* Wv     = (const float*)d_in[5];
    const float* bv     = (const float*)d_in[6];
    const float* Wo     = (const float*)d_in[7];
    const float* bo     = (const float*)d_in[8];
    const float* scale1 = (const float*)d_in[9];
    const float* scale2 = (const float*)d_in[10];
    const float* W1     = (const float*)d_in[11];
    const float* W2     = (const float*)d_in[12];
    const float* W3     = (const float*)d_in[13];
    float* out = (float*)d_out;

    __nv_bfloat16 *nH, *nL, *qkvH, *qkvL, *vTH, *vTL, *ctxH, *ctxL;
    __nv_bfloat16 *x1H, *x1L, *gH, *gL, *wH, *wL, *eH, *eL;
    float *h2, *x1;
    cudaGetSymbolAddress((void**)&nH, g_nH);     cudaGetSymbolAddress((void**)&nL, g_nL);
    cudaGetSymbolAddress((void**)&qkvH, g_qkvH); cudaGetSymbolAddress((void**)&qkvL, g_qkvL);
    cudaGetSymbolAddress((void**)&vTH, g_vTH);   cudaGetSymbolAddress((void**)&vTL, g_vTL);
    cudaGetSymbolAddress((void**)&ctxH, g_ctxH); cudaGetSymbolAddress((void**)&ctxL, g_ctxL);
    cudaGetSymbolAddress((void**)&h2, g_h2);
    cudaGetSymbolAddress((void**)&x1, g_x1);
    cudaGetSymbolAddress((void**)&x1H, g_x1H);   cudaGetSymbolAddress((void**)&x1L, g_x1L);
    cudaGetSymbolAddress((void**)&gH, g_gH);     cudaGetSymbolAddress((void**)&gL, g_gL);
    cudaGetSymbolAddress((void**)&wH, g_wH);     cudaGetSymbolAddress((void**)&wL, g_wL);
    cudaGetSymbolAddress((void**)&eH, g_eH);     cudaGetSymbolAddress((void**)&eL, g_eL);

    cudaFuncSetAttribute(gemm_bf16s, cudaFuncAttributeMaxDynamicSharedMemorySize, GEMM_SMEM);

    const float inv_sqrt_hd = 0.08838834764831845f;
    const long DSQ = (long)DD * DD;
    __nv_bfloat16 *WoH = wH + 3*DSQ, *WoL = wL + 3*DSQ;
    __nv_bfloat16 *W1H = wH + 4*DSQ, *W1L = wL + 4*DSQ;
    __nv_bfloat16 *W2H = wH + 5*DSQ, *W2L = wL + 5*DSQ;
    __nv_bfloat16 *W3H = wH + 6*DSQ, *W3L = wL + 6*DSQ;

    // 0. transpose + split weights to [N][K] bf16 hi/lo (q,k,v contiguous slices 0..2)
    dim3 tgridW(DD / 32, DD / 32, 1);
    transpose_split<<<tgridW, 256>>>(Wq, wH + 0*DSQ, wL + 0*DSQ, DD, DD, 0, 0, 0, 0, 1);
    transpose_split<<<tgridW, 256>>>(Wk, wH + 1*DSQ, wL + 1*DSQ, DD, DD, 0, 0, 0, 0, 1);
    transpose_split<<<tgridW, 256>>>(Wv, wH + 2*DSQ, wL + 2*DSQ, DD, DD, 0, 0, 0, 0, 1);
    transpose_split<<<tgridW, 256>>>(Wo, WoH, WoL, DD, DD, 0, 0, 0, 0, 1);
    transpose_split<<<tgridW, 256>>>(W1, W1H, W1L, DD, DD, 0, 0, 0, 0, 1);
    transpose_split<<<tgridW, 256>>>(W2, W2H, W2L, DD, DD, 0, 0, 0, 0, 1);
    transpose_split<<<tgridW, 256>>>(W3, W3H, W3L, DD, DD, 0, 0, 0, 0, 1);

    dim3 gridDense(DD / GBN, MM / GBM, 1);
    dim3 gridQKV(DD / GBN, MM / GBM, 3);
    dim3 gridQK(TT / GBN, TT / GBM, BB * NHH);
    dim3 gridPV(1, TT / GBM, BB * NHH);

    // 1. norm1
    rmsnorm_split<<<MM, 256>>>(x, scale1, nH, nL);

    // 2. Q/K/V projections in ONE launch (z selects weight slice / bias / output slice)
    gemm_bf16s<<<gridQKV, GTHREADS, GEMM_SMEM>>>(nH, nL, wH, wL, bq, bk, bv, nullptr,
        nullptr, qkvH, qkvL, DD, DD, DD, DD,
        0, 0, 0, DSQ, 0, ELEMS, 3, 1.0f, EPI_SPLIT);

    // 3. vT split: [b,h][d][t] from V slice (z=2)
    dim3 tgridV(HDD / 32, TT / 32, BB * NHH);
    transpose_split_bf2<<<tgridV, 256>>>(qkvH + 2*ELEMS, qkvL + 2*ELEMS, vTH, vTL,
        DD, TT,
        (long)TT * DD, (long)HDD,
        (long)NHH * HDD * TT, (long)HDD * TT, NHH);

    // 4. energy = Q K^T / sqrt(HD), written as split bf16
    gemm_bf16s<<<gridQK, GTHREADS, GEMM_SMEM>>>(qkvH, qkvL, qkvH + ELEMS, qkvL + ELEMS,
        nullptr, nullptr, nullptr, nullptr,
        nullptr, eH, eL,
        HDD, DD, DD, TT,
        (long)TT * DD, (long)HDD,
        (long)TT * DD, (long)HDD,
        (long)NHH * TT * TT, (long)TT * TT,
        NHH, inv_sqrt_hd, EPI_SPLIT);

    // 5+6. fused softmax + PV -> ctx (split)
    attn_pv<<<gridPV, 256>>>(eH, eL, vTH, vTL, ctxH, ctxL);

    // 7. h2 = ctx @ Wo + bo + x
    gemm_bf16s<<<gridDense, GTHREADS, GEMM_SMEM>>>(ctxH, ctxL, WoH, WoL, bo, nullptr, nullptr, x,
        h2, nullptr, nullptr, DD, DD, DD, DD, 0,0,0,0,0,0, 1, 1.0f, EPI_C);

    // 8. norm2
    rmsnorm_split<<<MM, 256>>>(h2, scale2, nH, nL);

    // 9. x1 = norm @ W1 (fp32 + split)
    gemm_bf16s<<<gridDense, GTHREADS, GEMM_SMEM>>>(nH, nL, W1H, W1L, nullptr, nullptr, nullptr, nullptr,
        x1, x1H, x1L, DD, DD, DD, DD, 0,0,0,0,0,0, 1, 1.0f, EPI_C | EPI_SPLIT);

    // 10+11. x2 = x1 @ W2 with fused swiglu: g = x1*sigmoid(x1)*x2 -> split
    gemm_bf16s<<<gridDense, GTHREADS, GEMM_SMEM>>>(x1H, x1L, W2H, W2L, nullptr, nullptr, nullptr, x1,
        nullptr, gH, gL, DD, DD, DD, DD, 0,0,0,0,0,0, 1, 1.0f, EPI_SWIGLU | EPI_SPLIT);

    // 12. out = g @ W3 + x
    gemm_bf16s<<<gridDense, GTHREADS, GEMM_SMEM>>>(gH, gL, W3H, W3L, nullptr, nullptr, nullptr, x,
        out, nullptr, nullptr, DD, DD, DD, DD, 0,0,0,0,0,0, 1, 1.0f, EPI_C);
}

// round 11
// speedup vs baseline: 1.6128x; 1.6128x over previous
#include <cuda_runtime.h>
#include <cuda_bf16.h>
#include <cstdint>
#include <math.h>

// ---------------- problem constants ----------------
#define BB  2
#define TT  2048
#define DD  2048
#define NHH 16
#define HDD 128
#define MM  (BB*TT)
#define ELEMS ((long)BB*TT*DD)
#define ESZ ((long)BB*NHH*TT*TT)

// GEMM tiling
#define GBM 128
#define GBN 128
#define GBK 32
#define GTHREADS 256

// SMEM: per stage 4 halves (AH, AL, BH, BL), 128 rows x 80B pitch each
#define PITCH 80
#define HALF_SZ 10240
#define STG 40960
#define NSTAGE 4
#define GEMM_SMEM (NSTAGE*STG)   // 163840 bytes

// epilogue modes (bitmask)
#define EPI_C      1   // write fp32 C (+resid)
#define EPI_SPLIT  2   // write split bf16 OH/OL of val
#define EPI_SWIGLU 4   // val = resid*sigmoid(resid)*val, then split write

// ---------------- scratch (static device memory) ----------------
__device__ __nv_bfloat16 g_nH[ELEMS], g_nL[ELEMS];
__device__ __nv_bfloat16 g_qkvH[3*ELEMS], g_qkvL[3*ELEMS];
__device__ __nv_bfloat16 g_vTH[ELEMS], g_vTL[ELEMS];
__device__ __nv_bfloat16 g_ctxH[ELEMS], g_ctxL[ELEMS];
__device__ float g_h2[ELEMS];
__device__ float g_x1[ELEMS];
__device__ __nv_bfloat16 g_x1H[ELEMS], g_x1L[ELEMS];
__device__ __nv_bfloat16 g_gH[ELEMS], g_gL[ELEMS];
__device__ __nv_bfloat16 g_wH[7L*DD*DD], g_wL[7L*DD*DD];
__device__ float g_energy[ESZ];
__device__ __nv_bfloat16 g_pH[ESZ], g_pL[ESZ];

// ---------------- helpers ----------------
__device__ __forceinline__ uint32_t smem_u32(const void* p) {
    uint32_t a;
    asm("{ .reg .u64 t; cvta.to.shared.u64 t, %1; cvt.u32.u64 %0, t; }" : "=r"(a) : "l"(p));
    return a;
}
__device__ __forceinline__ void ldsm4(uint32_t* r, uint32_t addr) {
    asm volatile("ldmatrix.sync.aligned.m8n8.x4.shared.b16 {%0,%1,%2,%3}, [%4];"
        : "=r"(r[0]), "=r"(r[1]), "=r"(r[2]), "=r"(r[3]) : "r"(addr));
}
__device__ __forceinline__ void mma_bf16(float* c, const uint32_t* a, const uint32_t* b) {
    asm volatile(
        "mma.sync.aligned.m16n8k16.row.col.f32.bf16.bf16.f32 "
        "{%0,%1,%2,%3}, {%4,%5,%6,%7}, {%8,%9}, {%0,%1,%2,%3};"
        : "+f"(c[0]), "+f"(c[1]), "+f"(c[2]), "+f"(c[3])
        : "r"(a[0]), "r"(a[1]), "r"(a[2]), "r"(a[3]), "r"(b[0]), "r"(b[1]));
}
__device__ __forceinline__ void cpasync16(uint32_t dst, const void* src) {
    asm volatile("cp.async.cg.shared.global [%0], [%1], 16;" :: "r"(dst), "l"(src));
}
#define CP_COMMIT() asm volatile("cp.async.commit_group;" ::: "memory")
#define CP_WAIT(N)  asm volatile("cp.async.wait_group %0;" :: "n"(N) : "memory")

__device__ __forceinline__ void split1(float v, __nv_bfloat16& h, __nv_bfloat16& l) {
    h = __float2bfloat16(v);
    l = __float2bfloat16(v - __bfloat162float(h));
}

// ---------------- bf16-split GEMM (4-stage cp.async pipeline) ----------------
__global__ __launch_bounds__(GTHREADS) void gemm_bf16s(
    const __nv_bfloat16* __restrict__ AH, const __nv_bfloat16* __restrict__ AL,
    const __nv_bfloat16* __restrict__ BH, const __nv_bfloat16* __restrict__ BL,
    const float* __restrict__ bias, const float* __restrict__ bias2, const float* __restrict__ bias3,
    const float* __restrict__ resid,
    float* __restrict__ C, __nv_bfloat16* __restrict__ OH, __nv_bfloat16* __restrict__ OL,
    int K, int lda, int ldb, int ldc,
    long sAb, long sAh, long sBb, long sBh, long sCb, long sCh, int nh,
    float alpha, int mode)
{
    extern __shared__ char smem[];
    const uint32_t sbase = smem_u32(smem);
    const int tid = threadIdx.x;
    const int wid = tid >> 5;
    const int lane = tid & 31;

    int z = blockIdx.z;
    int bz = z / nh, hz = z % nh;
    const long aoff = (long)bz * sAb + (long)hz * sAh;
    const long boff = (long)bz * sBb + (long)hz * sBh;
    const long coff = (long)bz * sCb + (long)hz * sCh;
    AH += aoff; AL += aoff;
    BH += boff; BL += boff;

    const float* bb = bias;
    if (bias2) bb = (hz == 0) ? bias : ((hz == 1) ? bias2 : bias3);

    const int bm = blockIdx.y * GBM;
    const int bn = blockIdx.x * GBN;

    const int wm = wid >> 2;
    const int wn = wid & 3;

    const uint32_t aOff = (uint32_t)(wm * 64 + (lane & 15)) * PITCH + (lane >> 4) * 16;
    const uint32_t bOff = 2 * HALF_SZ
        + (uint32_t)(wn * 32 + ((lane >> 4) << 3) + (lane & 7)) * PITCH + ((lane >> 3) & 1) * 16;

    const int cid0 = tid * 2, cid1 = cid0 + 1;
    const int r0 = cid0 >> 2, c0 = cid0 & 3;
    const int r1 = cid1 >> 2, c1 = cid1 & 3;
    const __nv_bfloat16* aH0 = AH + (long)(bm + r0) * lda + c0 * 8;
    const __nv_bfloat16* aH1 = AH + (long)(bm + r1) * lda + c1 * 8;
    const __nv_bfloat16* aL0 = AL + (long)(bm + r0) * lda + c0 * 8;
    const __nv_bfloat16* aL1 = AL + (long)(bm + r1) * lda + c1 * 8;
    const __nv_bfloat16* bH0 = BH + (long)(bn + r0) * ldb + c0 * 8;
    const __nv_bfloat16* bH1 = BH + (long)(bn + r1) * ldb + c1 * 8;
    const __nv_bfloat16* bL0 = BL + (long)(bn + r0) * ldb + c0 * 8;
    const __nv_bfloat16* bL1 = BL + (long)(bn + r1) * ldb + c1 * 8;
    const uint32_t d0 = (uint32_t)(r0 * PITCH + c0 * 16);
    const uint32_t d1 = (uint32_t)(r1 * PITCH + c1 * 16);

#define ISSUE_STAGE(SIDX, KO) do {                                   \
        uint32_t s_ = sbase + (uint32_t)(SIDX) * STG;                \
        long ko_ = (KO);                                             \
        cpasync16(s_ + d0,             aH0 + ko_);                   \
        cpasync16(s_ + d1,             aH1 + ko_);                   \
        cpasync16(s_ + HALF_SZ + d0,   aL0 + ko_);                   \
        cpasync16(s_ + HALF_SZ + d1,   aL1 + ko_);                   \
        cpasync16(s_ + 2*HALF_SZ + d0, bH0 + ko_);                   \
        cpasync16(s_ + 2*HALF_SZ + d1, bH1 + ko_);                   \
        cpasync16(s_ + 3*HALF_SZ + d0, bL0 + ko_);                   \
        cpasync16(s_ + 3*HALF_SZ + d1, bL1 + ko_);                   \
    } while (0)

    float acc[4][4][4];
    #pragma unroll
    for (int i = 0; i < 4; i++)
        #pragma unroll
        for (int j = 0; j < 4; j++)
            #pragma unroll
            for (int r = 0; r < 4; r++) acc[i][j][r] = 0.f;

    const int NKI = K / GBK;

    #pragma unroll
    for (int s = 0; s < NSTAGE - 1; s++) {
        if (s < NKI) ISSUE_STAGE(s, (long)s * GBK);
        CP_COMMIT();
    }

    for (int i = 0; i < NKI; i++) {
        CP_WAIT(2);
        __syncthreads();

        if (i + 3 < NKI) ISSUE_STAGE((i + 3) & (NSTAGE - 1), (long)(i + 3) * GBK);
        CP_COMMIT();

        const uint32_t sb = sbase + (uint32_t)(i & (NSTAGE - 1)) * STG;
        #pragma unroll
        for (int ks = 0; ks < 2; ks++) {
            uint32_t afh[4][4], afl[4][4];
            uint32_t bfh[2][4], bfl[2][4];
            #pragma unroll
            for (int mf = 0; mf < 4; mf++) {
                uint32_t ad = sb + aOff + mf * (16 * PITCH) + ks * 32;
                ldsm4(afh[mf], ad);
                ldsm4(afl[mf], ad + HALF_SZ);
            }
            #pragma unroll
            for (int np = 0; np < 2; np++) {
                uint32_t bd = sb + bOff + np * (16 * PITCH) + ks * 32;
                ldsm4(bfh[np], bd);
                ldsm4(bfl[np], bd + HALF_SZ);
            }
            #pragma unroll
            for (int mf = 0; mf < 4; mf++) {
                #pragma unroll
                for (int nf = 0; nf < 4; nf++) {
                    const int np = nf >> 1;
                    const int pr = (nf & 1) * 2;
                    mma_bf16(acc[mf][nf], afh[mf], &bfh[np][pr]);
                    mma_bf16(acc[mf][nf], afh[mf], &bfl[np][pr]);
                    mma_bf16(acc[mf][nf], afl[mf], &bfh[np][pr]);
                }
            }
        }
    }
#undef ISSUE_STAGE

    float* Cp = C ? C + coff : nullptr;
    __nv_bfloat16* OHp = OH ? OH + coff : nullptr;
    __nv_bfloat16* OLp = OL ? OL + coff : nullptr;
    const int g = lane >> 2;
    const int t = lane & 3;
    #pragma unroll
    for (int mf = 0; mf < 4; mf++) {
        #pragma unroll
        for (int nf = 0; nf < 4; nf++) {
            int row0 = bm + wm * 64 + mf * 16 + g;
            int col = bn + wn * 32 + nf * 8 + t * 2;
            float2 v0, v1;
            v0.x = acc[mf][nf][0] * alpha;
            v0.y = acc[mf][nf][1] * alpha;
            v1.x = acc[mf][nf][2] * alpha;
            v1.y = acc[mf][nf][3] * alpha;
            if (bb) {
                float2 bbv = *(const float2*)(bb + col);
                v0.x += bbv.x; v0.y += bbv.y;
                v1.x += bbv.x; v1.y += bbv.y;
            }
            long o0 = (long)row0 * ldc + col;
            long o1 = (long)(row0 + 8) * ldc + col;
            if (mode & EPI_SWIGLU) {
                float2 rr0 = *(const float2*)(resid + o0);
                float2 rr1 = *(const float2*)(resid + o1);
                v0.x = rr0.x * (1.0f / (1.0f + expf(-rr0.x))) * v0.x;
                v0.y = rr0.y * (1.0f / (1.0f + expf(-rr0.y))) * v0.y;
                v1.x = rr1.x * (1.0f / (1.0f + expf(-rr1.x))) * v1.x;
                v1.y = rr1.y * (1.0f / (1.0f + expf(-rr1.y))) * v1.y;
            }
            if (mode & EPI_SPLIT) {
                __nv_bfloat162 h0, l0, h1, l1;
                split1(v0.x, h0.x, l0.x); split1(v0.y, h0.y, l0.y);
                split1(v1.x, h1.x, l1.x); split1(v1.y, h1.y, l1.y);
                *(__nv_bfloat162*)(OHp + o0) = h0;
                *(__nv_bfloat162*)(OLp + o0) = l0;
                *(__nv_bfloat162*)(OHp + o1) = h1;
                *(__nv_bfloat162*)(OLp + o1) = l1;
            }
            if (mode & EPI_C) {
                if (resid) {
                    float2 rr0 = *(const float2*)(resid + o0);
                    float2 rr1 = *(const float2*)(resid + o1);
                    v0.x += rr0.x; v0.y += rr0.y;
                    v1.x += rr1.x; v1.y += rr1.y;
                }
                *(float2*)(Cp + o0) = v0;
                *(float2*)(Cp + o1) = v1;
            }
        }
    }
}

// ---------------- transpose + split (fp32 input) ----------------
__global__ __launch_bounds__(256) void transpose_split(
    const float* __restrict__ in, __nv_bfloat16* __restrict__ oH, __nv_bfloat16* __restrict__ oL,
    int ldin, int ldout, long sInB, long sInH, long sOutB, long sOutH, int nh)
{
    __shared__ float tile[32][33];
    int z = blockIdx.z, bz = z / nh, hz = z % nh;
    in += (long)bz * sInB + (long)hz * sInH;
    long ob = (long)bz * sOutB + (long)hz * sOutH;
    oH += ob; oL += ob;
    int c0 = blockIdx.x << 5, r0 = blockIdx.y << 5;
    int tx = threadIdx.x & 31, ty = threadIdx.x >> 5;
    #pragma unroll
    for (int j = 0; j < 4; j++)
        tile[ty + j * 8][tx] = in[(long)(r0 + ty + j * 8) * ldin + c0 + tx];
    __syncthreads();
    #pragma unroll
    for (int j = 0; j < 4; j++) {
        float val = tile[tx][ty + j * 8];
        __nv_bfloat16 h, l;
        split1(val, h, l);
        long o = (long)(c0 + ty + j * 8) * ldout + r0 + tx;
        oH[o] = h; oL[o] = l;
    }
}

// ---------------- transpose + split (bf16 hi/lo input) ----------------
__global__ __launch_bounds__(256) void transpose_split_bf2(
    const __nv_bfloat16* __restrict__ inH, const __nv_bfloat16* __restrict__ inL,
    __nv_bfloat16* __restrict__ oH, __nv_bfloat16* __restrict__ oL,
    int ldin, int ldout, long sInB, long sInH, long sOutB, long sOutH, int nh)
{
    __shared__ float tile[32][33];
    int z = blockIdx.z, bz = z / nh, hz = z % nh;
    long ib = (long)bz * sInB + (long)hz * sInH;
    inH += ib; inL += ib;
    long ob = (long)bz * sOutB + (long)hz * sOutH;
    oH += ob; oL += ob;
    int c0 = blockIdx.x << 5, r0 = blockIdx.y << 5;
    int tx = threadIdx.x & 31, ty = threadIdx.x >> 5;
    #pragma unroll
    for (int j = 0; j < 4; j++) {
        long idx = (long)(r0 + ty + j * 8) * ldin + c0 + tx;
        tile[ty + j * 8][tx] = __bfloat162float(inH[idx]) + __bfloat162float(inL[idx]);
    }
    __syncthreads();
    #pragma unroll
    for (int j = 0; j < 4; j++) {
        float val = tile[tx][ty + j * 8];
        __nv_bfloat16 h, l;
        split1(val, h, l);
        long o = (long)(c0 + ty + j * 8) * ldout + r0 + tx;
        oH[o] = h; oL[o] = l;
    }
}

// ---------------- block reductions ----------------
__device__ __forceinline__ float block_reduce_sum(float v) {
    __shared__ float sh[8];
    #pragma unroll
    for (int o = 16; o > 0; o >>= 1) v += __shfl_xor_sync(0xffffffffu, v, o);
    int w = threadIdx.x >> 5;
    if ((threadIdx.x & 31) == 0) sh[w] = v;
    __syncthreads();
    if (threadIdx.x < 8) {
        v = sh[threadIdx.x];
        #pragma unroll
        for (int o = 4; o > 0; o >>= 1) v += __shfl_xor_sync(0xffu, v, o);
        if (threadIdx.x == 0) sh[0] = v;
    }
    __syncthreads();
    float r = sh[0];
    __syncthreads();
    return r;
}
__device__ __forceinline__ float block_reduce_max(float v) {
    __shared__ float sh[8];
    #pragma unroll
    for (int o = 16; o > 0; o >>= 1) v = fmaxf(v, __shfl_xor_sync(0xffffffffu, v, o));
    int w = threadIdx.x >> 5;
    if ((threadIdx.x & 31) == 0) sh[w] = v;
    __syncthreads();
    if (threadIdx.x < 8) {
        v = sh[threadIdx.x];
        #pragma unroll
        for (int o = 4; o > 0; o >>= 1) v = fmaxf(v, __shfl_xor_sync(0xffu, v, o));
        if (threadIdx.x == 0) sh[0] = v;
    }
    __syncthreads();
    float r = sh[0];
    __syncthreads();
    return r;
}

// ---------------- RMSNorm -> split bf16 ----------------
__global__ __launch_bounds__(256) void rmsnorm_split(
    const float* __restrict__ x, const float* __restrict__ scale,
    __nv_bfloat16* __restrict__ yH, __nv_bfloat16* __restrict__ yL)
{
    long row = blockIdx.x;
    const float* xr = x + row * (long)DD;
    float vals[8];
    float ss = 0.f;
    #pragma unroll
    for (int i = 0; i < 8; i++) {
        int idx = threadIdx.x + i * 256;
        float v = xr[idx];
        vals[i] = v;
        ss += v * v;
    }
    ss = block_reduce_sum(ss);
    float r = rsqrtf(ss * (1.0f / DD) + 1e-5f);
    long base = row * (long)DD;
    #pragma unroll
    for (int i = 0; i < 8; i++) {
        int idx = threadIdx.x + i * 256;
        float v = scale[idx] * vals[i] * r;
        __nv_bfloat16 h, l;
        split1(v, h, l);
        yH[base + idx] = h; yL[base + idx] = l;
    }
}

// ---------------- softmax -> split bf16 probs (vectorized) ----------------
__global__ __launch_bounds__(256) void softmax_split(
    const float* __restrict__ e,
    __nv_bfloat16* __restrict__ pH, __nv_bfloat16* __restrict__ pL)
{
    long base = (long)blockIdx.x * TT;
    const float4* p4 = (const float4*)(e + base);
    float4 vals[2];
    float m = -1e30f;
    #pragma unroll
    for (int i = 0; i < 2; i++) {
        vals[i] = p4[threadIdx.x + i * 256];
        m = fmaxf(m, fmaxf(fmaxf(vals[i].x, vals[i].y), fmaxf(vals[i].z, vals[i].w)));
    }
    m = block_reduce_max(m);
    float s = 0.f;
    #pragma unroll
    for (int i = 0; i < 2; i++) {
        vals[i].x = expf(vals[i].x - m);
        vals[i].y = expf(vals[i].y - m);
        vals[i].z = expf(vals[i].z - m);
        vals[i].w = expf(vals[i].w - m);
        s += vals[i].x + vals[i].y + vals[i].z + vals[i].w;
    }
    s = block_reduce_sum(s);
    float inv = 1.0f / s;
    #pragma unroll
    for (int i = 0; i < 2; i++) {
        long o = base + (threadIdx.x + i * 256) * 4;
        __nv_bfloat162 h0, l0, h1, l1;
        split1(vals[i].x * inv, h0.x, l0.x);
        split1(vals[i].y * inv, h0.y, l0.y);
        split1(vals[i].z * inv, h1.x, l1.x);
        split1(vals[i].w * inv, h1.y, l1.y);
        *(__nv_bfloat162*)(pH + o) = h0;
        *(__nv_bfloat162*)(pH + o + 2) = h1;
        *(__nv_bfloat162*)(pL + o) = l0;
        *(__nv_bfloat162*)(pL + o + 2) = l1;
    }
}

// ---------------- launcher ----------------
extern "C" void kernel_launch(void* const* d_in, const int* in_sizes, int n_in,
                              void* d_out, int out_size) {
    const float* x      = (const float*)d_in[0];
    const float* Wq     = (const float*)d_in[1];
    const float* bq     = (const float*)d_in[2];
    const float* Wk     = (const float*)d_in[3];
    const float* bk     = (const float*)d_in[4];
    const float* Wv     = (const float*)d_in[5];
    const float* bv     = (const float*)d_in[6];
    const float* Wo     = (const float*)d_in[7];
    const float* bo     = (const float*)d_in[8];
    const float* scale1 = (const float*)d_in[9];
    const float* scale2 = (const float*)d_in[10];
    const float* W1     = (const float*)d_in[11];
    const float* W2     = (const float*)d_in[12];
    const float* W3     = (const float*)d_in[13];
    float* out = (float*)d_out;

    __nv_bfloat16 *nH, *nL, *qkvH, *qkvL, *vTH, *vTL, *ctxH, *ctxL;
    __nv_bfloat16 *x1H, *x1L, *gH, *gL, *wH, *wL, *pH, *pL;
    float *h2, *x1, *energy;
    cudaGetSymbolAddress((void**)&nH, g_nH);     cudaGetSymbolAddress((void**)&nL, g_nL);
    cudaGetSymbolAddress((void**)&qkvH, g_qkvH); cudaGetSymbolAddress((void**)&qkvL, g_qkvL);
    cudaGetSymbolAddress((void**)&vTH, g_vTH);   cudaGetSymbolAddress((void**)&vTL, g_vTL);
    cudaGetSymbolAddress((void**)&ctxH, g_ctxH); cudaGetSymbolAddress((void**)&ctxL, g_ctxL);
    cudaGetSymbolAddress((void**)&h2, g_h2);
    cudaGetSymbolAddress((void**)&x1, g_x1);
    cudaGetSymbolAddress((void**)&x1H, g_x1H);   cudaGetSymbolAddress((void**)&x1L, g_x1L);
    cudaGetSymbolAddress((void**)&gH, g_gH);     cudaGetSymbolAddress((void**)&gL, g_gL);
    cudaGetSymbolAddress((void**)&wH, g_wH);     cudaGetSymbolAddress((void**)&wL, g_wL);
    cudaGetSymbolAddress((void**)&pH, g_pH);     cudaGetSymbolAddress((void**)&pL, g_pL);
    cudaGetSymbolAddress((void**)&energy, g_energy);

    cudaFuncSetAttribute(gemm_bf16s, cudaFuncAttributeMaxDynamicSharedMemorySize, GEMM_SMEM);

    const float inv_sqrt_hd = 0.08838834764831845f;
    const long DSQ = (long)DD * DD;
    __nv_bfloat16 *WoH = wH + 3*DSQ, *WoL = wL + 3*DSQ;
    __nv_bfloat16 *W1H = wH + 4*DSQ, *W1L = wL + 4*DSQ;
    __nv_bfloat16 *W2H = wH + 5*DSQ, *W2L = wL + 5*DSQ;
    __nv_bfloat16 *W3H = wH + 6*DSQ, *W3L = wL + 6*DSQ;

    // 0. transpose + split weights to [N][K] bf16 hi/lo (q,k,v contiguous slices 0..2)
    dim3 tgridW(DD / 32, DD / 32, 1);
    transpose_split<<<tgridW, 256>>>(Wq, wH + 0*DSQ, wL + 0*DSQ, DD, DD, 0, 0, 0, 0, 1);
    transpose_split<<<tgridW, 256>>>(Wk, wH + 1*DSQ, wL + 1*DSQ, DD, DD, 0, 0, 0, 0, 1);
    transpose_split<<<tgridW, 256>>>(Wv, wH + 2*DSQ, wL + 2*DSQ, DD, DD, 0, 0, 0, 0, 1);
    transpose_split<<<tgridW, 256>>>(Wo, WoH, WoL, DD, DD, 0, 0, 0, 0, 1);
    transpose_split<<<tgridW, 256>>>(W1, W1H, W1L, DD, DD, 0, 0, 0, 0, 1);
    transpose_split<<<tgridW, 256>>>(W2, W2H, W2L, DD, DD, 0, 0, 0, 0, 1);
    transpose_split<<<tgridW, 256>>>(W3, W3H, W3L, DD, DD, 0, 0, 0, 0, 1);

    dim3 gridDense(DD / GBN, MM / GBM, 1);
    dim3 gridQKV(DD / GBN, MM / GBM, 3);
    dim3 gridQK(TT / GBN, TT / GBM, BB * NHH);
    dim3 gridPV(1, TT / GBM, BB * NHH);

    // 1. norm1
    rmsnorm_split<<<MM, 256>>>(x, scale1, nH, nL);

    // 2. Q/K/V projections in ONE launch (z selects weight slice / bias / output slice)
    gemm_bf16s<<<gridQKV, GTHREADS, GEMM_SMEM>>>(nH, nL, wH, wL, bq, bk, bv, nullptr,
        nullptr, qkvH, qkvL, DD, DD, DD, DD,
        0, 0, 0, DSQ, 0, ELEMS, 3, 1.0f, EPI_SPLIT);

    // 3. vT split: [b,h][d][t] from V slice (z=2)
    dim3 tgridV(HDD / 32, TT / 32, BB * NHH);
    transpose_split_bf2<<<tgridV, 256>>>(qkvH + 2*ELEMS, qkvL + 2*ELEMS, vTH, vTL,
        DD, TT,
        (long)TT * DD, (long)HDD,
        (long)NHH * HDD * TT, (long)HDD * TT, NHH);

    // 4. energy = Q K^T / sqrt(HD)  (fp32)
    gemm_bf16s<<<gridQK, GTHREADS, GEMM_SMEM>>>(qkvH, qkvL, qkvH + ELEMS, qkvL + ELEMS,
        nullptr, nullptr, nullptr, nullptr,
        energy, nullptr, nullptr,
        HDD, DD, DD, TT,
        (long)TT * DD, (long)HDD,
        (long)TT * DD, (long)HDD,
        (long)NHH * TT * TT, (long)TT * TT,
        NHH, inv_sqrt_hd, EPI_C);

    // 5. softmax -> split probs
    softmax_split<<<BB * NHH * TT, 256>>>(energy, pH, pL);

    // 6. ctx = P @ V
    gemm_bf16s<<<gridPV, GTHREADS, GEMM_SMEM>>>(pH, pL, vTH, vTL,
        nullptr, nullptr, nullptr, nullptr,
        nullptr, ctxH, ctxL,
        TT, TT, TT, DD,
        (long)NHH * TT * TT, (long)TT * TT,
        (long)NHH * HDD * TT, (long)HDD * TT,
        (long)TT * DD, (long)HDD,
        NHH, 1.0f, EPI_SPLIT);

    // 7. h2 = ctx @ Wo + bo + x
    gemm_bf16s<<<gridDense, GTHREADS, GEMM_SMEM>>>(ctxH, ctxL, WoH, WoL, bo, nullptr, nullptr, x,
        h2, nullptr, nullptr, DD, DD, DD, DD, 0,0,0,0,0,0, 1, 1.0f, EPI_C);

    // 8. norm2
    rmsnorm_split<<<MM, 256>>>(h2, scale2, nH, nL);

    // 9. x1 = norm @ W1 (fp32 + split)
    gemm_bf16s<<<gridDense, GTHREADS, GEMM_SMEM>>>(nH, nL, W1H, W1L, nullptr, nullptr, nullptr, nullptr,
        x1, x1H, x1L, DD, DD, DD, DD, 0,0,0,0,0,0, 1, 1.0f, EPI_C | EPI_SPLIT);

    // 10+11. x2 = x1 @ W2 with fused swiglu: g = x1*sigmoid(x1)*x2 -> split
    gemm_bf16s<<<gridDense, GTHREADS, GEMM_SMEM>>>(x1H, x1L, W2H, W2L, nullptr, nullptr, nullptr, x1,
        nullptr, gH, gL, DD, DD, DD, DD, 0,0,0,0,0,0, 1, 1.0f, EPI_SWIGLU | EPI_SPLIT);

    // 12. out = g @ W3 + x
    gemm_bf16s<<<gridDense, GTHREADS, GEMM_SMEM>>>(gH, gL, W3H, W3L, nullptr, nullptr, nullptr, x,
        out, nullptr, nullptr, DD, DD, DD, DD, 0,0,0,0,0,0, 1, 1.0f, EPI_C);
}

// round 12
// speedup vs baseline: 1.8889x; 1.1712x over previous
#include <cuda_runtime.h>
#include <cuda_bf16.h>
#include <cstdint>
#include <math.h>

// ---------------- problem constants ----------------
#define BB  2
#define TT  2048
#define DD  2048
#define NHH 16
#define HDD 128
#define MM  (BB*TT)
#define ELEMS ((long)BB*TT*DD)
#define ESZ ((long)BB*NHH*TT*TT)

// GEMM tiling
#define GBM 128
#define GBN 128
#define GBK 32
#define GTHREADS 256

// SMEM: per stage 4 halves (AH, AL, BH, BL), 128 rows x 80B pitch each
#define PITCH 80
#define HALF_SZ 10240
#define STG 40960
#define NSTAGE 2
#define GEMM_SMEM (NSTAGE*STG)   // 81920 bytes -> 2 CTAs/SM

// epilogue modes (bitmask)
#define EPI_C      1   // write fp32 C (+resid)
#define EPI_SPLIT  2   // write split bf16 OH/OL of val
#define EPI_SWIGLU 4   // val = resid*sigmoid(resid)*val, then split write

// ---------------- scratch (static device memory) ----------------
__device__ __nv_bfloat16 g_nH[ELEMS], g_nL[ELEMS];
__device__ __nv_bfloat16 g_qkvH[3*ELEMS], g_qkvL[3*ELEMS];
__device__ __nv_bfloat16 g_vTH[ELEMS], g_vTL[ELEMS];
__device__ __nv_bfloat16 g_ctxH[ELEMS], g_ctxL[ELEMS];
__device__ float g_h2[ELEMS];
__device__ float g_x1[ELEMS];
__device__ __nv_bfloat16 g_x1H[ELEMS], g_x1L[ELEMS];
__device__ __nv_bfloat16 g_gH[ELEMS], g_gL[ELEMS];
__device__ __nv_bfloat16 g_wH[7L*DD*DD], g_wL[7L*DD*DD];
__device__ float g_energy[ESZ];
__device__ __nv_bfloat16 g_pH[ESZ], g_pL[ESZ];

// ---------------- helpers ----------------
__device__ __forceinline__ uint32_t smem_u32(const void* p) {
    uint32_t a;
    asm("{ .reg .u64 t; cvta.to.shared.u64 t, %1; cvt.u32.u64 %0, t; }" : "=r"(a) : "l"(p));
    return a;
}
__device__ __forceinline__ void ldsm4(uint32_t* r, uint32_t addr) {
    asm volatile("ldmatrix.sync.aligned.m8n8.x4.shared.b16 {%0,%1,%2,%3}, [%4];"
        : "=r"(r[0]), "=r"(r[1]), "=r"(r[2]), "=r"(r[3]) : "r"(addr));
}
__device__ __forceinline__ void mma_bf16(float* c, const uint32_t* a, const uint32_t* b) {
    asm volatile(
        "mma.sync.aligned.m16n8k16.row.col.f32.bf16.bf16.f32 "
        "{%0,%1,%2,%3}, {%4,%5,%6,%7}, {%8,%9}, {%0,%1,%2,%3};"
        : "+f"(c[0]), "+f"(c[1]), "+f"(c[2]), "+f"(c[3])
        : "r"(a[0]), "r"(a[1]), "r"(a[2]), "r"(a[3]), "r"(b[0]), "r"(b[1]));
}
__device__ __forceinline__ void cpasync16(uint32_t dst, const void* src) {
    asm volatile("cp.async.cg.shared.global [%0], [%1], 16;" :: "r"(dst), "l"(src));
}
#define CP_COMMIT() asm volatile("cp.async.commit_group;" ::: "memory")
#define CP_WAIT(N)  asm volatile("cp.async.wait_group %0;" :: "n"(N) : "memory")

__device__ __forceinline__ void split1(float v, __nv_bfloat16& h, __nv_bfloat16& l) {
    h = __float2bfloat16(v);
    l = __float2bfloat16(v - __bfloat162float(h));
}

// ---------------- bf16-split GEMM (2-stage cp.async pipeline, 2 CTAs/SM) ----------------
__global__ __launch_bounds__(GTHREADS, 2) void gemm_bf16s(
    const __nv_bfloat16* __restrict__ AH, const __nv_bfloat16* __restrict__ AL,
    const __nv_bfloat16* __restrict__ BH, const __nv_bfloat16* __restrict__ BL,
    const float* __restrict__ bias, const float* __restrict__ bias2, const float* __restrict__ bias3,
    const float* __restrict__ resid,
    float* __restrict__ C, __nv_bfloat16* __restrict__ OH, __nv_bfloat16* __restrict__ OL,
    int K, int lda, int ldb, int ldc,
    long sAb, long sAh, long sBb, long sBh, long sCb, long sCh, int nh,
    float alpha, int mode)
{
    extern __shared__ char smem[];
    const uint32_t sbase = smem_u32(smem);
    const int tid = threadIdx.x;
    const int wid = tid >> 5;
    const int lane = tid & 31;

    int z = blockIdx.z;
    int bz = z / nh, hz = z % nh;
    const long aoff = (long)bz * sAb + (long)hz * sAh;
    const long boff = (long)bz * sBb + (long)hz * sBh;
    const long coff = (long)bz * sCb + (long)hz * sCh;
    AH += aoff; AL += aoff;
    BH += boff; BL += boff;

    const float* bb = bias;
    if (bias2) bb = (hz == 0) ? bias : ((hz == 1) ? bias2 : bias3);

    const int bm = blockIdx.y * GBM;
    const int bn = blockIdx.x * GBN;

    const int wm = wid >> 2;
    const int wn = wid & 3;

    const uint32_t aOff = (uint32_t)(wm * 64 + (lane & 15)) * PITCH + (lane >> 4) * 16;
    const uint32_t bOff = 2 * HALF_SZ
        + (uint32_t)(wn * 32 + ((lane >> 4) << 3) + (lane & 7)) * PITCH + ((lane >> 3) & 1) * 16;

    const int cid0 = tid * 2, cid1 = cid0 + 1;
    const int r0 = cid0 >> 2, c0 = cid0 & 3;
    const int r1 = cid1 >> 2, c1 = cid1 & 3;
    const __nv_bfloat16* aH0 = AH + (long)(bm + r0) * lda + c0 * 8;
    const __nv_bfloat16* aH1 = AH + (long)(bm + r1) * lda + c1 * 8;
    const __nv_bfloat16* aL0 = AL + (long)(bm + r0) * lda + c0 * 8;
    const __nv_bfloat16* aL1 = AL + (long)(bm + r1) * lda + c1 * 8;
    const __nv_bfloat16* bH0 = BH + (long)(bn + r0) * ldb + c0 * 8;
    const __nv_bfloat16* bH1 = BH + (long)(bn + r1) * ldb + c1 * 8;
    const __nv_bfloat16* bL0 = BL + (long)(bn + r0) * ldb + c0 * 8;
    const __nv_bfloat16* bL1 = BL + (long)(bn + r1) * ldb + c1 * 8;
    const uint32_t d0 = (uint32_t)(r0 * PITCH + c0 * 16);
    const uint32_t d1 = (uint32_t)(r1 * PITCH + c1 * 16);

#define ISSUE_STAGE(SIDX, KO) do {                                   \
        uint32_t s_ = sbase + (uint32_t)(SIDX) * STG;                \
        long ko_ = (KO);                                             \
        cpasync16(s_ + d0,             aH0 + ko_);                   \
        cpasync16(s_ + d1,             aH1 + ko_);                   \
        cpasync16(s_ + HALF_SZ + d0,   aL0 + ko_);                   \
        cpasync16(s_ + HALF_SZ + d1,   aL1 + ko_);                   \
        cpasync16(s_ + 2*HALF_SZ + d0, bH0 + ko_);                   \
        cpasync16(s_ + 2*HALF_SZ + d1, bH1 + ko_);                   \
        cpasync16(s_ + 3*HALF_SZ + d0, bL0 + ko_);                   \
        cpasync16(s_ + 3*HALF_SZ + d1, bL1 + ko_);                   \
    } while (0)

    float acc[4][4][4];
    #pragma unroll
    for (int i = 0; i < 4; i++)
        #pragma unroll
        for (int j = 0; j < 4; j++)
            #pragma unroll
            for (int r = 0; r < 4; r++) acc[i][j][r] = 0.f;

    const int NKI = K / GBK;

    // prologue: issue stage 0
    ISSUE_STAGE(0, 0L);
    CP_COMMIT();

    for (int i = 0; i < NKI; i++) {
        CP_WAIT(0);          // stage i arrived (issued one iteration earlier)
        __syncthreads();     // all warps done computing stage i-1 -> other buffer free

        if (i + 1 < NKI) ISSUE_STAGE((i + 1) & (NSTAGE - 1), (long)(i + 1) * GBK);
        CP_COMMIT();

        const uint32_t sb = sbase + (uint32_t)(i & (NSTAGE - 1)) * STG;
        #pragma unroll
        for (int ks = 0; ks < 2; ks++) {
            uint32_t afh[4][4], afl[4][4];
            uint32_t bfh[2][4], bfl[2][4];
            #pragma unroll
            for (int mf = 0; mf < 4; mf++) {
                uint32_t ad = sb + aOff + mf * (16 * PITCH) + ks * 32;
                ldsm4(afh[mf], ad);
                ldsm4(afl[mf], ad + HALF_SZ);
            }
            #pragma unroll
            for (int np = 0; np < 2; np++) {
                uint32_t bd = sb + bOff + np * (16 * PITCH) + ks * 32;
                ldsm4(bfh[np], bd);
                ldsm4(bfl[np], bd + HALF_SZ);
            }
            #pragma unroll
            for (int mf = 0; mf < 4; mf++) {
                #pragma unroll
                for (int nf = 0; nf < 4; nf++) {
                    const int np = nf >> 1;
                    const int pr = (nf & 1) * 2;
                    mma_bf16(acc[mf][nf], afh[mf], &bfh[np][pr]);
                    mma_bf16(acc[mf][nf], afh[mf], &bfl[np][pr]);
                    mma_bf16(acc[mf][nf], afl[mf], &bfh[np][pr]);
                }
            }
        }
        __syncthreads();     // reads of stage i done before next iter's cp.async overwrite
    }
#undef ISSUE_STAGE

    float* Cp = C ? C + coff : nullptr;
    __nv_bfloat16* OHp = OH ? OH + coff : nullptr;
    __nv_bfloat16* OLp = OL ? OL + coff : nullptr;
    const int g = lane >> 2;
    const int t = lane & 3;
    #pragma unroll
    for (int mf = 0; mf < 4; mf++) {
        #pragma unroll
        for (int nf = 0; nf < 4; nf++) {
            int row0 = bm + wm * 64 + mf * 16 + g;
            int col = bn + wn * 32 + nf * 8 + t * 2;
            float2 v0, v1;
            v0.x = acc[mf][nf][0] * alpha;
            v0.y = acc[mf][nf][1] * alpha;
            v1.x = acc[mf][nf][2] * alpha;
            v1.y = acc[mf][nf][3] * alpha;
            if (bb) {
                float2 bbv = *(const float2*)(bb + col);
                v0.x += bbv.x; v0.y += bbv.y;
                v1.x += bbv.x; v1.y += bbv.y;
            }
            long o0 = (long)row0 * ldc + col;
            long o1 = (long)(row0 + 8) * ldc + col;
            if (mode & EPI_SWIGLU) {
                float2 rr0 = *(const float2*)(resid + o0);
                float2 rr1 = *(const float2*)(resid + o1);
                v0.x = rr0.x * (1.0f / (1.0f + expf(-rr0.x))) * v0.x;
                v0.y = rr0.y * (1.0f / (1.0f + expf(-rr0.y))) * v0.y;
                v1.x = rr1.x * (1.0f / (1.0f + expf(-rr1.x))) * v1.x;
                v1.y = rr1.y * (1.0f / (1.0f + expf(-rr1.y))) * v1.y;
            }
            if (mode & EPI_SPLIT) {
                __nv_bfloat162 h0, l0, h1, l1;
                split1(v0.x, h0.x, l0.x); split1(v0.y, h0.y, l0.y);
                split1(v1.x, h1.x, l1.x); split1(v1.y, h1.y, l1.y);
                *(__nv_bfloat162*)(OHp + o0) = h0;
                *(__nv_bfloat162*)(OLp + o0) = l0;
                *(__nv_bfloat162*)(OHp + o1) = h1;
                *(__nv_bfloat162*)(OLp + o1) = l1;
            }
            if (mode & EPI_C) {
                if (resid) {
                    float2 rr0 = *(const float2*)(resid + o0);
                    float2 rr1 = *(const float2*)(resid + o1);
                    v0.x += rr0.x; v0.y += rr0.y;
                    v1.x += rr1.x; v1.y += rr1.y;
                }
                *(float2*)(Cp + o0) = v0;
                *(float2*)(Cp + o1) = v1;
            }
        }
    }
}

// ---------------- transpose + split (fp32 input) ----------------
__global__ __launch_bounds__(256) void transpose_split(
    const float* __restrict__ in, __nv_bfloat16* __restrict__ oH, __nv_bfloat16* __restrict__ oL,
    int ldin, int ldout, long sInB, long sInH, long sOutB, long sOutH, int nh)
{
    __shared__ float tile[32][33];
    int z = blockIdx.z, bz = z / nh, hz = z % nh;
    in += (long)bz * sInB + (long)hz * sInH;
    long ob = (long)bz * sOutB + (long)hz * sOutH;
    oH += ob; oL += ob;
    int c0 = blockIdx.x << 5, r0 = blockIdx.y << 5;
    int tx = threadIdx.x & 31, ty = threadIdx.x >> 5;
    #pragma unroll
    for (int j = 0; j < 4; j++)
        tile[ty + j * 8][tx] = in[(long)(r0 + ty + j * 8) * ldin + c0 + tx];
    __syncthreads();
    #pragma unroll
    for (int j = 0; j < 4; j++) {
        float val = tile[tx][ty + j * 8];
        __nv_bfloat16 h, l;
        split1(val, h, l);
        long o = (long)(c0 + ty + j * 8) * ldout + r0 + tx;
        oH[o] = h; oL[o] = l;
    }
}

// ---------------- transpose + split (bf16 hi/lo input) ----------------
__global__ __launch_bounds__(256) void transpose_split_bf2(
    const __nv_bfloat16* __restrict__ inH, const __nv_bfloat16* __restrict__ inL,
    __nv_bfloat16* __restrict__ oH, __nv_bfloat16* __restrict__ oL,
    int ldin, int ldout, long sInB, long sInH, long sOutB, long sOutH, int nh)
{
    __shared__ float tile[32][33];
    int z = blockIdx.z, bz = z / nh, hz = z % nh;
    long ib = (long)bz * sInB + (long)hz * sInH;
    inH += ib; inL += ib;
    long ob = (long)bz * sOutB + (long)hz * sOutH;
    oH += ob; oL += ob;
    int c0 = blockIdx.x << 5, r0 = blockIdx.y << 5;
    int tx = threadIdx.x & 31, ty = threadIdx.x >> 5;
    #pragma unroll
    for (int j = 0; j < 4; j++) {
        long idx = (long)(r0 + ty + j * 8) * ldin + c0 + tx;
        tile[ty + j * 8][tx] = __bfloat162float(inH[idx]) + __bfloat162float(inL[idx]);
    }
    __syncthreads();
    #pragma unroll
    for (int j = 0; j < 4; j++) {
        float val = tile[tx][ty + j * 8];
        __nv_bfloat16 h, l;
        split1(val, h, l);
        long o = (long)(c0 + ty + j * 8) * ldout + r0 + tx;
        oH[o] = h; oL[o] = l;
    }
}

// ---------------- block reductions ----------------
__device__ __forceinline__ float block_reduce_sum(float v) {
    __shared__ float sh[8];
    #pragma unroll
    for (int o = 16; o > 0; o >>= 1) v += __shfl_xor_sync(0xffffffffu, v, o);
    int w = threadIdx.x >> 5;
    if ((threadIdx.x & 31) == 0) sh[w] = v;
    __syncthreads();
    if (threadIdx.x < 8) {
        v = sh[threadIdx.x];
        #pragma unroll
        for (int o = 4; o > 0; o >>= 1) v += __shfl_xor_sync(0xffu, v, o);
        if (threadIdx.x == 0) sh[0] = v;
    }
    __syncthreads();
    float r = sh[0];
    __syncthreads();
    return r;
}
__device__ __forceinline__ float block_reduce_max(float v) {
    __shared__ float sh[8];
    #pragma unroll
    for (int o = 16; o > 0; o >>= 1) v = fmaxf(v, __shfl_xor_sync(0xffffffffu, v, o));
    int w = threadIdx.x >> 5;
    if ((threadIdx.x & 31) == 0) sh[w] = v;
    __syncthreads();
    if (threadIdx.x < 8) {
        v = sh[threadIdx.x];
        #pragma unroll
        for (int o = 4; o > 0; o >>= 1) v = fmaxf(v, __shfl_xor_sync(0xffu, v, o));
        if (threadIdx.x == 0) sh[0] = v;
    }
    __syncthreads();
    float r = sh[0];
    __syncthreads();
    return r;
}

// ---------------- RMSNorm -> split bf16 ----------------
__global__ __launch_bounds__(256) void rmsnorm_split(
    const float* __restrict__ x, const float* __restrict__ scale,
    __nv_bfloat16* __restrict__ yH, __nv_bfloat16* __restrict__ yL)
{
    long row = blockIdx.x;
    const float* xr = x + row * (long)DD;
    float vals[8];
    float ss = 0.f;
    #pragma unroll
    for (int i = 0; i < 8; i++) {
        int idx = threadIdx.x + i * 256;
        float v = xr[idx];
        vals[i] = v;
        ss += v * v;
    }
    ss = block_reduce_sum(ss);
    float r = rsqrtf(ss * (1.0f / DD) + 1e-5f);
    long base = row * (long)DD;
    #pragma unroll
    for (int i = 0; i < 8; i++) {
        int idx = threadIdx.x + i * 256;
        float v = scale[idx] * vals[i] * r;
        __nv_bfloat16 h, l;
        split1(v, h, l);
        yH[base + idx] = h; yL[base + idx] = l;
    }
}

// ---------------- softmax -> split bf16 probs (vectorized) ----------------
__global__ __launch_bounds__(256) void softmax_split(
    const float* __restrict__ e,
    __nv_bfloat16* __restrict__ pH, __nv_bfloat16* __restrict__ pL)
{
    long base = (long)blockIdx.x * TT;
    const float4* p4 = (const float4*)(e + base);
    float4 vals[2];
    float m = -1e30f;
    #pragma unroll
    for (int i = 0; i < 2; i++) {
        vals[i] = p4[threadIdx.x + i * 256];
        m = fmaxf(m, fmaxf(fmaxf(vals[i].x, vals[i].y), fmaxf(vals[i].z, vals[i].w)));
    }
    m = block_reduce_max(m);
    float s = 0.f;
    #pragma unroll
    for (int i = 0; i < 2; i++) {
        vals[i].x = expf(vals[i].x - m);
        vals[i].y = expf(vals[i].y - m);
        vals[i].z = expf(vals[i].z - m);
        vals[i].w = expf(vals[i].w - m);
        s += vals[i].x + vals[i].y + vals[i].z + vals[i].w;
    }
    s = block_reduce_sum(s);
    float inv = 1.0f / s;
    #pragma unroll
    for (int i = 0; i < 2; i++) {
        long o = base + (threadIdx.x + i * 256) * 4;
        __nv_bfloat162 h0, l0, h1, l1;
        split1(vals[i].x * inv, h0.x, l0.x);
        split1(vals[i].y * inv, h0.y, l0.y);
        split1(vals[i].z * inv, h1.x, l1.x);
        split1(vals[i].w * inv, h1.y, l1.y);
        *(__nv_bfloat162*)(pH + o) = h0;
        *(__nv_bfloat162*)(pH + o + 2) = h1;
        *(__nv_bfloat162*)(pL + o) = l0;
        *(__nv_bfloat162*)(pL + o + 2) = l1;
    }
}

// ---------------- launcher ----------------
extern "C" void kernel_launch(void* const* d_in, const int* in_sizes, int n_in,
                              void* d_out, int out_size) {
    const float* x      = (const float*)d_in[0];
    const float* Wq     = (const float*)d_in[1];
    const float* bq     = (const float*)d_in[2];
    const float* Wk     = (const float*)d_in[3];
    const float* bk     = (const float*)d_in[4];
    const float* Wv     = (const float*)d_in[5];
    const float* bv     = (const float*)d_in[6];
    const float* Wo     = (const float*)d_in[7];
    const float* bo     = (const float*)d_in[8];
    const float* scale1 = (const float*)d_in[9];
    const float* scale2 = (const float*)d_in[10];
    const float* W1     = (const float*)d_in[11];
    const float* W2     = (const float*)d_in[12];
    const float* W3     = (const float*)d_in[13];
    float* out = (float*)d_out;

    __nv_bfloat16 *nH, *nL, *qkvH, *qkvL, *vTH, *vTL, *ctxH, *ctxL;
    __nv_bfloat16 *x1H, *x1L, *gH, *gL, *wH, *wL, *pH, *pL;
    float *h2, *x1, *energy;
    cudaGetSymbolAddress((void**)&nH, g_nH);     cudaGetSymbolAddress((void**)&nL, g_nL);
    cudaGetSymbolAddress((void**)&qkvH, g_qkvH); cudaGetSymbolAddress((void**)&qkvL, g_qkvL);
    cudaGetSymbolAddress((void**)&vTH, g_vTH);   cudaGetSymbolAddress((void**)&vTL, g_vTL);
    cudaGetSymbolAddress((void**)&ctxH, g_ctxH); cudaGetSymbolAddress((void**)&ctxL, g_ctxL);
    cudaGetSymbolAddress((void**)&h2, g_h2);
    cudaGetSymbolAddress((void**)&x1, g_x1);
    cudaGetSymbolAddress((void**)&x1H, g_x1H);   cudaGetSymbolAddress((void**)&x1L, g_x1L);
    cudaGetSymbolAddress((void**)&gH, g_gH);     cudaGetSymbolAddress((void**)&gL, g_gL);
    cudaGetSymbolAddress((void**)&wH, g_wH);     cudaGetSymbolAddress((void**)&wL, g_wL);
    cudaGetSymbolAddress((void**)&pH, g_pH);     cudaGetSymbolAddress((void**)&pL, g_pL);
    cudaGetSymbolAddress((void**)&energy, g_energy);

    cudaFuncSetAttribute(gemm_bf16s, cudaFuncAttributeMaxDynamicSharedMemorySize, GEMM_SMEM);

    const float inv_sqrt_hd = 0.08838834764831845f;
    const long DSQ = (long)DD * DD;
    __nv_bfloat16 *WoH = wH + 3*DSQ, *WoL = wL + 3*DSQ;
    __nv_bfloat16 *W1H = wH + 4*DSQ, *W1L = wL + 4*DSQ;
    __nv_bfloat16 *W2H = wH + 5*DSQ, *W2L = wL + 5*DSQ;
    __nv_bfloat16 *W3H = wH + 6*DSQ, *W3L = wL + 6*DSQ;

    // 0. transpose + split weights to [N][K] bf16 hi/lo (q,k,v contiguous slices 0..2)
    dim3 tgridW(DD / 32, DD / 32, 1);
    transpose_split<<<tgridW, 256>>>(Wq, wH + 0*DSQ, wL + 0*DSQ, DD, DD, 0, 0, 0, 0, 1);
    transpose_split<<<tgridW, 256>>>(Wk, wH + 1*DSQ, wL + 1*DSQ, DD, DD, 0, 0, 0, 0, 1);
    transpose_split<<<tgridW, 256>>>(Wv, wH + 2*DSQ, wL + 2*DSQ, DD, DD, 0, 0, 0, 0, 1);
    transpose_split<<<tgridW, 256>>>(Wo, WoH, WoL, DD, DD, 0, 0, 0, 0, 1);
    transpose_split<<<tgridW, 256>>>(W1, W1H, W1L, DD, DD, 0, 0, 0, 0, 1);
    transpose_split<<<tgridW, 256>>>(W2, W2H, W2L, DD, DD, 0, 0, 0, 0, 1);
    transpose_split<<<tgridW, 256>>>(W3, W3H, W3L, DD, DD, 0, 0, 0, 0, 1);

    dim3 gridDense(DD / GBN, MM / GBM, 1);
    dim3 gridQKV(DD / GBN, MM / GBM, 3);
    dim3 gridQK(TT / GBN, TT / GBM, BB * NHH);
    dim3 gridPV(1, TT / GBM, BB * NHH);

    // 1. norm1
    rmsnorm_split<<<MM, 256>>>(x, scale1, nH, nL);

    // 2. Q/K/V projections in ONE launch (z selects weight slice / bias / output slice)
    gemm_bf16s<<<gridQKV, GTHREADS, GEMM_SMEM>>>(nH, nL, wH, wL, bq, bk, bv, nullptr,
        nullptr, qkvH, qkvL, DD, DD, DD, DD,
        0, 0, 0, DSQ, 0, ELEMS, 3, 1.0f, EPI_SPLIT);

    // 3. vT split: [b,h][d][t] from V slice (z=2)
    dim3 tgridV(HDD / 32, TT / 32, BB * NHH);
    transpose_split_bf2<<<tgridV, 256>>>(qkvH + 2*ELEMS, qkvL + 2*ELEMS, vTH, vTL,
        DD, TT,
        (long)TT * DD, (long)HDD,
        (long)NHH * HDD * TT, (long)HDD * TT, NHH);

    // 4. energy = Q K^T / sqrt(HD)  (fp32)
    gemm_bf16s<<<gridQK, GTHREADS, GEMM_SMEM>>>(qkvH, qkvL, qkvH + ELEMS, qkvL + ELEMS,
        nullptr, nullptr, nullptr, nullptr,
        energy, nullptr, nullptr,
        HDD, DD, DD, TT,
        (long)TT * DD, (long)HDD,
        (long)TT * DD, (long)HDD,
        (long)NHH * TT * TT, (long)TT * TT,
        NHH, inv_sqrt_hd, EPI_C);

    // 5. softmax -> split probs
    softmax_split<<<BB * NHH * TT, 256>>>(energy, pH, pL);

    // 6. ctx = P @ V
    gemm_bf16s<<<gridPV, GTHREADS, GEMM_SMEM>>>(pH, pL, vTH, vTL,
        nullptr, nullptr, nullptr, nullptr,
        nullptr, ctxH, ctxL,
        TT, TT, TT, DD,
        (long)NHH * TT * TT, (long)TT * TT,
        (long)NHH * HDD * TT, (long)HDD * TT,
        (long)TT * DD, (long)HDD,
        NHH, 1.0f, EPI_SPLIT);

    // 7. h2 = ctx @ Wo + bo + x
    gemm_bf16s<<<gridDense, GTHREADS, GEMM_SMEM>>>(ctxH, ctxL, WoH, WoL, bo, nullptr, nullptr, x,
        h2, nullptr, nullptr, DD, DD, DD, DD, 0,0,0,0,0,0, 1, 1.0f, EPI_C);

    // 8. norm2
    rmsnorm_split<<<MM, 256>>>(h2, scale2, nH, nL);

    // 9. x1 = norm @ W1 (fp32 + split)
    gemm_bf16s<<<gridDense, GTHREADS, GEMM_SMEM>>>(nH, nL, W1H, W1L, nullptr, nullptr, nullptr, nullptr,
        x1, x1H, x1L, DD, DD, DD, DD, 0,0,0,0,0,0, 1, 1.0f, EPI_C | EPI_SPLIT);

    // 10+11. x2 = x1 @ W2 with fused swiglu: g = x1*sigmoid(x1)*x2 -> split
    gemm_bf16s<<<gridDense, GTHREADS, GEMM_SMEM>>>(x1H, x1L, W2H, W2L, nullptr, nullptr, nullptr, x1,
        nullptr, gH, gL, DD, DD, DD, DD, 0,0,0,0,0,0, 1, 1.0f, EPI_SWIGLU | EPI_SPLIT);

    // 12. out = g @ W3 + x
    gemm_bf16s<<<gridDense, GTHREADS, GEMM_SMEM>>>(gH, gL, W3H, W3L, nullptr, nullptr, nullptr, x,
        out, nullptr, nullptr, DD, DD, DD, DD, 0,0,0,0,0,0, 1, 1.0f, EPI_C);
}